// round 16
// baseline (speedup 1.0000x reference)
#include <cuda_runtime.h>
#include <cuda_fp16.h>
#include <cstdint>

#define N_NODES 20000
#define N_EDGES 320000
#define IN_CH   256
#define HID_CH  256
#define OUT_CH  128
#define KDIM    256
#define DETECT_E 2048
#define CAP     96      // max in-degree capacity (Poisson(16): P(>96) ~ 1e-40)

// ---------------- scratch (device globals; no allocation) ----------------
__device__ int    g_cnt [N_NODES];
__device__ int    g_bucket[N_NODES * CAP];
__device__ __half g_z   [N_NODES * HID_CH];   // fp16 messenger (post-GEMM, row-scaled)
__device__ float  g_h1  [N_NODES * HID_CH];   // layer1 output (fp32, GEMM2 input)
__device__ int    g_is64 = 1;   // static default; only ever cleared

// ---------------- helpers ----------------
__device__ __forceinline__ void cp16(uint32_t saddr, const void* gptr) {
    asm volatile("cp.async.cg.shared.global [%0], [%1], 16;" :: "r"(saddr), "l"(gptr));
}
#define CP_COMMIT() asm volatile("cp.async.commit_group;" ::: "memory")
#define CP_WAIT(n)  asm volatile("cp.async.wait_group %0;" :: "n"(n) : "memory")

__device__ __forceinline__ uint32_t rna(float x) {   // round-to-nearest tf32 bits
    uint32_t u; asm("cvt.rna.tf32.f32 %0, %1;" : "=r"(u) : "f"(x)); return u;
}

// accumulate 8 halves (one uint4) into fp32 accumulators
__device__ __forceinline__ void hadd8(float* acc, uint4 u) {
    const __half2* h = (const __half2*)&u;
    #pragma unroll
    for (int i = 0; i < 4; i++) {
        float2 f = __half22float2(h[i]);
        acc[2 * i]     += f.x;
        acc[2 * i + 1] += f.y;
    }
}
// pairwise fp16 add of two uint4s (8 HADD2-lanes)
__device__ __forceinline__ uint4 hpair(uint4 a, uint4 b) {
    const __half2* ha = (const __half2*)&a;
    const __half2* hb = (const __half2*)&b;
    uint4 r;
    __half2* hr = (__half2*)&r;
    #pragma unroll
    for (int i = 0; i < 4; i++) hr[i] = __hadd2(ha[i], hb[i]);
    return r;
}

// ---------------- init: zero counters + dtype probe ----------------
__global__ void k_init(const unsigned int* __restrict__ w) {
    int i = blockIdx.x * blockDim.x + threadIdx.x;
    if (i < N_NODES) g_cnt[i] = 0;
    if (blockIdx.x == 0) {
        for (int j = threadIdx.x; j < DETECT_E; j += blockDim.x)
            if (w[2 * j + 1] != 0) g_is64 = 0;   // int32 layout detected
    }
}

// ---------------- bucket build: 4 edges per thread, vector index loads ----------------
__global__ void k_build(const void* __restrict__ ei) {
    int e0 = (blockIdx.x * blockDim.x + threadIdx.x) * 4;
    if (e0 >= N_EDGES) return;
    int s[4], d[4];
    if (g_is64) {
        const long long* p = (const long long*)ei;
        #pragma unroll
        for (int i = 0; i < 4; i++) {
            s[i] = (int)p[e0 + i];
            d[i] = (int)p[N_EDGES + e0 + i];
        }
    } else {
        const int* p = (const int*)ei;
        int4 sv = *(const int4*)&p[e0];
        int4 dv = *(const int4*)&p[N_EDGES + e0];
        s[0] = sv.x; s[1] = sv.y; s[2] = sv.z; s[3] = sv.w;
        d[0] = dv.x; d[1] = dv.y; d[2] = dv.z; d[3] = dv.w;
    }
    #pragma unroll
    for (int i = 0; i < 4; i++) {
        int pos = atomicAdd(&g_cnt[d[i]], 1);
        if (pos < CAP) g_bucket[d[i] * CAP + pos] = s[i];
    }
}

// ---------------- TF32 mma.sync GEMM, cp.async double-buffered ----------------
// B staged directly from W[K][N]; epilogue scales by dinv[row], writes fp16.
#define PADA   36
#define ASTAGE (128 * PADA)
#define PADN   136
#define BSTAGE (32 * PADN)
#define GEMM_SMEM ((2 * ASTAGE + 2 * BSTAGE) * 4)   // 71680 bytes
__global__ __launch_bounds__(256) void mma_gemm(const float* __restrict__ A,
                                                const float* __restrict__ W,
                                                __half* __restrict__ C, int M, int N) {
    constexpr int KC = 32;
    extern __shared__ float sm[];
    float* Asm = sm;
    float* Bsm = sm + 2 * ASTAGE;

    int tid  = threadIdx.x;
    int wid  = tid >> 5;
    int lane = tid & 31;
    int g = lane >> 2;
    int t = lane & 3;

    int rowBase = blockIdx.x * 128;
    int colBase = blockIdx.y * 128;
    int wm = wid & 3;
    int wn = wid >> 2;

    float acc[2][8][4];
    #pragma unroll
    for (int i = 0; i < 2; i++)
        #pragma unroll
        for (int j = 0; j < 8; j++)
            #pragma unroll
            for (int q = 0; q < 4; q++) acc[i][j][q] = 0.0f;

    uint32_t sA = (uint32_t)__cvta_generic_to_shared(Asm);
    uint32_t sB = (uint32_t)__cvta_generic_to_shared(Bsm);

    int arow[4], ac4[4], brow[4], bc4[4];
    #pragma unroll
    for (int it = 0; it < 4; it++) {
        int f = tid + it * 256;
        arow[it] = f >> 3;  ac4[it] = (f & 7) << 2;
        brow[it] = f >> 5;  bc4[it] = (f & 31) << 2;
    }

    auto stage_load = [&](int s, int k0) {
        #pragma unroll
        for (int it = 0; it < 4; it++) {
            int gr = rowBase + arow[it];
            if (gr >= M) gr = M - 1;               // clamp; rows discarded at store
            cp16(sA + (s * ASTAGE + arow[it] * PADA + ac4[it]) * 4,
                 &A[(size_t)gr * KDIM + k0 + ac4[it]]);
            cp16(sB + (s * BSTAGE + brow[it] * PADN + bc4[it]) * 4,
                 &W[(size_t)(k0 + brow[it]) * N + colBase + bc4[it]]);
        }
        CP_COMMIT();
    };

    stage_load(0, 0);

    constexpr int NCH = KDIM / KC;
    for (int c = 0; c < NCH; c++) {
        int buf = c & 1;
        if (c + 1 < NCH) { stage_load(buf ^ 1, (c + 1) * KC); CP_WAIT(1); }
        else             { CP_WAIT(0); }
        __syncthreads();

        const float* Ab = Asm + buf * ASTAGE;
        const float* Bb = Bsm + buf * BSTAGE;
        #pragma unroll
        for (int kk = 0; kk < KC; kk += 8) {
            uint32_t a[2][4];
            #pragma unroll
            for (int mf = 0; mf < 2; mf++) {
                int r0 = wm * 32 + mf * 16 + g;
                a[mf][0] = rna(Ab[r0 * PADA + kk + t]);
                a[mf][1] = rna(Ab[(r0 + 8) * PADA + kk + t]);
                a[mf][2] = rna(Ab[r0 * PADA + kk + t + 4]);
                a[mf][3] = rna(Ab[(r0 + 8) * PADA + kk + t + 4]);
            }
            uint32_t b[8][2];
            #pragma unroll
            for (int nf = 0; nf < 8; nf++) {
                int n0 = wn * 64 + nf * 8 + g;
                b[nf][0] = rna(Bb[(kk + t) * PADN + n0]);
                b[nf][1] = rna(Bb[(kk + t + 4) * PADN + n0]);
            }
            #pragma unroll
            for (int mf = 0; mf < 2; mf++)
                #pragma unroll
                for (int nf = 0; nf < 8; nf++) {
                    asm volatile(
                        "mma.sync.aligned.m16n8k8.row.col.f32.tf32.tf32.f32 "
                        "{%0,%1,%2,%3}, {%4,%5,%6,%7}, {%8,%9}, {%0,%1,%2,%3};"
                        : "+f"(acc[mf][nf][0]), "+f"(acc[mf][nf][1]),
                          "+f"(acc[mf][nf][2]), "+f"(acc[mf][nf][3])
                        : "r"(a[mf][0]), "r"(a[mf][1]), "r"(a[mf][2]), "r"(a[mf][3]),
                          "r"(b[nf][0]), "r"(b[nf][1]));
                }
        }
        __syncthreads();
    }

    #pragma unroll
    for (int mf = 0; mf < 2; mf++) {
        int r0 = rowBase + wm * 32 + mf * 16 + g;
        float di0 = (r0     < M) ? rsqrtf((float)(g_cnt[r0]     + 1)) : 0.f;
        float di1 = (r0 + 8 < M) ? rsqrtf((float)(g_cnt[r0 + 8] + 1)) : 0.f;
        #pragma unroll
        for (int nf = 0; nf < 8; nf++) {
            int c0 = colBase + wn * 64 + nf * 8 + t * 2;
            if (r0 < M)
                *(__half2*)&C[(size_t)r0 * N + c0] =
                    __float22half2_rn(make_float2(acc[mf][nf][0] * di0,
                                                  acc[mf][nf][1] * di0));
            if (r0 + 8 < M)
                *(__half2*)&C[(size_t)(r0 + 8) * N + c0] =
                    __float22half2_rn(make_float2(acc[mf][nf][2] * di1,
                                                  acc[mf][nf][3] * di1));
        }
    }
}

// ---------------- bucket gather: vector index loads, 8-edge unroll ----------------
// out[d] = dinv[d]*(sum_{s->d} z[s] + z[d]) + b
template <int CH, bool RELU>
__global__ void k_gather(const __half* __restrict__ z,
                         const float* __restrict__ b,
                         float* __restrict__ out) {
    constexpr int TPN = CH / 8;      // threads per node, 8 halves (16B) each
    constexpr int NPB = 256 / TPN;
    int lane = threadIdx.x % TPN;
    int node = blockIdx.x * NPB + threadIdx.x / TPN;
    if (node >= N_NODES) return;

    int cnt = g_cnt[node];
    int m = min(cnt, CAP);
    const int* bk = &g_bucket[node * CAP];
    const int co = lane * 8;

    float acc[8] = {0.f, 0.f, 0.f, 0.f, 0.f, 0.f, 0.f, 0.f};
    int p = 0;
    for (; p + 8 <= m; p += 8) {
        int4 i0 = *(const int4*)&bk[p];        // one LDG.128 = 4 indices
        int4 i1 = *(const int4*)&bk[p + 4];
        uint4 u0 = *(const uint4*)&z[(size_t)i0.x * CH + co];
        uint4 u1 = *(const uint4*)&z[(size_t)i0.y * CH + co];
        uint4 u2 = *(const uint4*)&z[(size_t)i0.z * CH + co];
        uint4 u3 = *(const uint4*)&z[(size_t)i0.w * CH + co];
        uint4 u4 = *(const uint4*)&z[(size_t)i1.x * CH + co];
        uint4 u5 = *(const uint4*)&z[(size_t)i1.y * CH + co];
        uint4 u6 = *(const uint4*)&z[(size_t)i1.z * CH + co];
        uint4 u7 = *(const uint4*)&z[(size_t)i1.w * CH + co];
        hadd8(acc, hpair(u0, u1));
        hadd8(acc, hpair(u2, u3));
        hadd8(acc, hpair(u4, u5));
        hadd8(acc, hpair(u6, u7));
    }
    if (p + 4 <= m) {
        int4 i0 = *(const int4*)&bk[p];
        uint4 u0 = *(const uint4*)&z[(size_t)i0.x * CH + co];
        uint4 u1 = *(const uint4*)&z[(size_t)i0.y * CH + co];
        uint4 u2 = *(const uint4*)&z[(size_t)i0.z * CH + co];
        uint4 u3 = *(const uint4*)&z[(size_t)i0.w * CH + co];
        hadd8(acc, hpair(u0, u1));
        hadd8(acc, hpair(u2, u3));
        p += 4;
    }
    for (; p < m; p++) {
        uint4 u = *(const uint4*)&z[(size_t)bk[p] * CH + co];
        hadd8(acc, u);
    }
    // self loop
    {
        uint4 u = *(const uint4*)&z[(size_t)node * CH + co];
        hadd8(acc, u);
    }

    float di = rsqrtf((float)(cnt + 1));
    float4 b0 = *(const float4*)&b[co];
    float4 b1 = *(const float4*)&b[co + 4];
    float r[8];
    r[0] = acc[0] * di + b0.x; r[1] = acc[1] * di + b0.y;
    r[2] = acc[2] * di + b0.z; r[3] = acc[3] * di + b0.w;
    r[4] = acc[4] * di + b1.x; r[5] = acc[5] * di + b1.y;
    r[6] = acc[6] * di + b1.z; r[7] = acc[7] * di + b1.w;
    if (RELU) {
        #pragma unroll
        for (int i = 0; i < 8; i++) r[i] = fmaxf(r[i], 0.f);
    }
    *(float4*)&out[(size_t)node * CH + co]     = make_float4(r[0], r[1], r[2], r[3]);
    *(float4*)&out[(size_t)node * CH + co + 4] = make_float4(r[4], r[5], r[6], r[7]);
}

// ---------------- launch ----------------
extern "C" void kernel_launch(void* const* d_in, const int* in_sizes, int n_in,
                              void* d_out, int out_size) {
    const float* x   = (const float*)d_in[0];
    const void*  ei  = d_in[1];
    const float* W1  = (const float*)d_in[2];
    const float* b1  = (const float*)d_in[3];
    const float* W2  = (const float*)d_in[4];
    const float* b2  = (const float*)d_in[5];
    float*       out = (float*)d_out;

    __half* p_z;
    float*  p_h1;
    cudaGetSymbolAddress((void**)&p_z,  g_z);
    cudaGetSymbolAddress((void**)&p_h1, g_h1);

    cudaFuncSetAttribute(mma_gemm, cudaFuncAttributeMaxDynamicSharedMemorySize, GEMM_SMEM);

    // 0) init (zero counters + dtype probe)
    k_init<<<(N_NODES + 255) / 256, 256>>>((const unsigned int*)ei);

    // 1) adjacency buckets + degrees (4 edges/thread)
    k_build<<<(N_EDGES / 4 + 255) / 256, 256>>>(ei);

    const int MT = (N_NODES + 127) / 128;  // 157 row tiles

    // 2) layer 1: z1 = half((x @ W1) * dinv) ; h1 = relu(dinv*(sum z1 + self) + b1)
    {
        dim3 grid(MT, HID_CH / 128);
        mma_gemm<<<grid, 256, GEMM_SMEM>>>(x, W1, p_z, N_NODES, HID_CH);
    }
    {
        constexpr int NPB = 256 / (HID_CH / 8);   // 8 nodes per block
        k_gather<HID_CH, true><<<(N_NODES + NPB - 1) / NPB, 256>>>(p_z, b1, p_h1);
    }

    // 3) layer 2: z2 = half((h1 @ W2) * dinv) ; out = dinv*(sum z2 + self) + b2
    {
        dim3 grid(MT, OUT_CH / 128);
        mma_gemm<<<grid, 256, GEMM_SMEM>>>(p_h1, W2, p_z, N_NODES, OUT_CH);
    }
    {
        constexpr int NPB = 256 / (OUT_CH / 8);   // 16 nodes per block
        k_gather<OUT_CH, false><<<(N_NODES + NPB - 1) / NPB, 256>>>(p_z, b2, out);
    }
}